// round 1
// baseline (speedup 1.0000x reference)
#include <cuda_runtime.h>
#include <math.h>

#define BSZ   8192
#define INP   300
#define HD    1000
#define YPAD  304      // 300 padded to multiple of 16
#define HPAD  1008     // 1000 padded to multiple of 16
#define NTOP  10
#define RHO_STAR 0.15f

#define OFF_H    (BSZ * INP)            // 2457600
#define OFF_SCAL (OFF_H + BSZ * HD)     // 10649600

// ---------------- static device scratch (no allocations allowed) ----------------
__device__ __align__(16) float g_yn[BSZ * YPAD];          // normalized y, zero-padded
__device__ __align__(16) float g_hn[BSZ * HPAD];          // normalized h, zero-padded
__device__ __align__(16) float g_M[BSZ * BSZ];            // 256 MB similarity matrix scratch
__device__ float g_topy[BSZ * NTOP];
__device__ float g_toph[BSZ * NTOP];
__device__ float g_colsum[HD];
__device__ float g_recon;
__device__ float g_psl;

// ---------------- helpers ----------------
__device__ __forceinline__ float blockReduceSum(float v) {
    __shared__ float sh[32];
    int lane = threadIdx.x & 31;
    int wid  = threadIdx.x >> 5;
    #pragma unroll
    for (int o = 16; o > 0; o >>= 1) v += __shfl_down_sync(0xffffffffu, v, o);
    if (lane == 0) sh[wid] = v;
    __syncthreads();
    int nw = (blockDim.x + 31) >> 5;
    v = (threadIdx.x < nw) ? sh[lane] : 0.0f;
    if (wid == 0) {
        #pragma unroll
        for (int o = 16; o > 0; o >>= 1) v += __shfl_down_sync(0xffffffffu, v, o);
    }
    return v;  // valid on thread 0
}

// ---------------- init accumulators (must run every replay) ----------------
__global__ void init_accum_kernel() {
    int t = threadIdx.x;
    if (t < HD) g_colsum[t] = 0.0f;
    if (t == HD)     g_recon = 0.0f;
    if (t == HD + 1) g_psl   = 0.0f;
}

// ---------------- row normalization ----------------
__global__ void normalize_y_kernel(const float* __restrict__ y) {
    int row = blockIdx.x;
    int t = threadIdx.x;                 // 128 threads
    float s = 0.0f;
    for (int k = t; k < INP; k += 128) { float v = y[row * INP + k]; s += v * v; }
    float tot = blockReduceSum(s);
    __shared__ float snrm;
    if (t == 0) snrm = fmaxf(sqrtf(tot), 1e-6f);
    __syncthreads();
    float inv = 1.0f / snrm;
    for (int k = t; k < YPAD; k += 128)
        g_yn[row * YPAD + k] = (k < INP) ? y[row * INP + k] * inv : 0.0f;
}

__global__ void normalize_h_kernel(const float* __restrict__ h) {
    int row = blockIdx.x;
    int t = threadIdx.x;                 // 256 threads
    float s = 0.0f;
    for (int k = t; k < HD; k += 256) { float v = h[row * HD + k]; s += v * v; }
    float tot = blockReduceSum(s);
    __shared__ float snrm;
    if (t == 0) snrm = fmaxf(sqrtf(tot), 1e-6f);
    __syncthreads();
    float inv = 1.0f / snrm;
    for (int k = t; k < HPAD; k += 256)
        g_hn[row * HPAD + k] = (k < HD) ? h[row * HD + k] * inv : 0.0f;
}

// ---------------- generic C = act(A @ B^T + bias); A:[M,K], B:[N,K] ----------------
// 128x128 tile, BK=16, 256 threads, 8x8 micro-tile. Guarded (ragged M/N/K ok).
template <int ACT>   // 0 = none, 1 = clip01
__global__ __launch_bounds__(256, 2)
void gemm_abt_kernel(const float* __restrict__ A, const float* __restrict__ Bm,
                     const float* __restrict__ bias, float* __restrict__ C,
                     int M, int N, int K) {
    __shared__ float As[16][132];
    __shared__ float Bs[16][132];
    int tid = threadIdx.x;
    int tx = tid & 15, ty = tid >> 4;
    int rb = blockIdx.y * 128, cb = blockIdx.x * 128;
    float acc[8][8] = {};
    for (int kk = 0; kk < K; kk += 16) {
        #pragma unroll
        for (int l = 0; l < 8; l++) {
            int e = l * 256 + tid;
            int r = e >> 4, k = e & 15;
            int gk = kk + k;
            int ga = rb + r;
            As[k][r] = (ga < M && gk < K) ? A[(size_t)ga * K + gk] : 0.0f;
            int gb = cb + r;
            Bs[k][r] = (gb < N && gk < K) ? Bm[(size_t)gb * K + gk] : 0.0f;
        }
        __syncthreads();
        #pragma unroll
        for (int k = 0; k < 16; k++) {
            float a[8], b[8];
            #pragma unroll
            for (int i = 0; i < 8; i++) a[i] = As[k][ty * 8 + i];
            #pragma unroll
            for (int j = 0; j < 8; j++) b[j] = Bs[k][tx * 8 + j];
            #pragma unroll
            for (int i = 0; i < 8; i++)
                #pragma unroll
                for (int j = 0; j < 8; j++) acc[i][j] += a[i] * b[j];
        }
        __syncthreads();
    }
    #pragma unroll
    for (int i = 0; i < 8; i++) {
        int gr = rb + ty * 8 + i;
        if (gr >= M) continue;
        #pragma unroll
        for (int j = 0; j < 8; j++) {
            int gc = cb + tx * 8 + j;
            if (gc >= N) continue;
            float v = acc[i][j] + bias[gc];
            if (ACT == 1) v = fminf(fmaxf(v, 0.0f), 1.0f);
            C[(size_t)gr * N + gc] = v;
        }
    }
}

// ---------------- symmetric Gram: g_M = A @ A^T, A:[8192, KPAD], KPAD % 16 == 0 ----
// Upper-triangular blocks only; writes tile and its transpose. Unguarded float4 loads.
template <int KPAD, int WHICH>   // WHICH: 0 = g_yn, 1 = g_hn
__global__ __launch_bounds__(256, 2)
void symgemm_kernel() {
    int bi = blockIdx.y, bj = blockIdx.x;
    if (bi > bj) return;
    const float* __restrict__ A = (WHICH == 0) ? g_yn : g_hn;
    __shared__ float As[16][132];
    __shared__ float Bs[16][132];
    int tid = threadIdx.x;
    int tx = tid & 15, ty = tid >> 4;
    const float* Ar = A + (size_t)bi * 128 * KPAD;
    const float* Br = A + (size_t)bj * 128 * KPAD;
    float acc[8][8] = {};
    for (int kk = 0; kk < KPAD; kk += 16) {
        #pragma unroll
        for (int l = 0; l < 2; l++) {
            int e = l * 256 + tid;
            int r = e >> 2;
            int k4 = (e & 3) * 4;
            float4 va = *(const float4*)&Ar[(size_t)r * KPAD + kk + k4];
            As[k4 + 0][r] = va.x; As[k4 + 1][r] = va.y;
            As[k4 + 2][r] = va.z; As[k4 + 3][r] = va.w;
            float4 vb = *(const float4*)&Br[(size_t)r * KPAD + kk + k4];
            Bs[k4 + 0][r] = vb.x; Bs[k4 + 1][r] = vb.y;
            Bs[k4 + 2][r] = vb.z; Bs[k4 + 3][r] = vb.w;
        }
        __syncthreads();
        #pragma unroll
        for (int k = 0; k < 16; k++) {
            float a[8], b[8];
            #pragma unroll
            for (int i = 0; i < 8; i++) a[i] = As[k][ty * 8 + i];
            #pragma unroll
            for (int j = 0; j < 8; j++) b[j] = Bs[k][tx * 8 + j];
            #pragma unroll
            for (int i = 0; i < 8; i++)
                #pragma unroll
                for (int j = 0; j < 8; j++) acc[i][j] += a[i] * b[j];
        }
        __syncthreads();
    }
    int r0 = bi * 128 + ty * 8;
    int c0 = bj * 128 + tx * 8;
    #pragma unroll
    for (int i = 0; i < 8; i++) {
        float4 v0 = make_float4(acc[i][0], acc[i][1], acc[i][2], acc[i][3]);
        float4 v1 = make_float4(acc[i][4], acc[i][5], acc[i][6], acc[i][7]);
        *(float4*)&g_M[(size_t)(r0 + i) * BSZ + c0]     = v0;
        *(float4*)&g_M[(size_t)(r0 + i) * BSZ + c0 + 4] = v1;
    }
    if (bi != bj) {
        #pragma unroll
        for (int j = 0; j < 8; j++) {
            float4 v0 = make_float4(acc[0][j], acc[1][j], acc[2][j], acc[3][j]);
            float4 v1 = make_float4(acc[4][j], acc[5][j], acc[6][j], acc[7][j]);
            *(float4*)&g_M[(size_t)(c0 + j) * BSZ + r0]     = v0;
            *(float4*)&g_M[(size_t)(c0 + j) * BSZ + r0 + 4] = v1;
        }
    }
}

// ---------------- row-wise top-10 (diag skipped == set to -10) ----------------
template <int WHICH>   // 0 -> g_topy, 1 -> g_toph
__global__ void topk_kernel() {
    int row = blockIdx.x;
    int tid = threadIdx.x;               // 128 threads
    float* outTop = (WHICH == 0) ? g_topy : g_toph;
    const float* Mr = g_M + (size_t)row * BSZ;
    float best[NTOP];
    #pragma unroll
    for (int i = 0; i < NTOP; i++) best[i] = -1e30f;
    for (int j = tid; j < BSZ; j += 128) {
        if (j == row) continue;
        float v = Mr[j];
        if (v > best[NTOP - 1]) {
            best[NTOP - 1] = v;
            #pragma unroll
            for (int i = NTOP - 1; i > 0; --i) {
                if (best[i] > best[i - 1]) {
                    float t = best[i - 1]; best[i - 1] = best[i]; best[i] = t;
                }
            }
        }
    }
    __shared__ float sB[128 * NTOP];
    __shared__ float sV[128];
    __shared__ int   sI[128];
    #pragma unroll
    for (int i = 0; i < NTOP; i++) sB[tid * NTOP + i] = best[i];
    __syncthreads();
    int p = 0;
    for (int r = 0; r < NTOP; r++) {
        sV[tid] = (p < NTOP) ? sB[tid * NTOP + p] : -1e30f;
        sI[tid] = tid;
        __syncthreads();
        for (int s = 64; s > 0; s >>= 1) {
            if (tid < s) {
                if (sV[tid + s] > sV[tid]) { sV[tid] = sV[tid + s]; sI[tid] = sI[tid + s]; }
            }
            __syncthreads();
        }
        if (tid == 0) outTop[row * NTOP + r] = sV[0];
        int w = sI[0];
        if (tid == w) p++;
        __syncthreads();
    }
}

// ---------------- scalar reductions ----------------
__global__ void recon_kernel(const float* __restrict__ outp, const float* __restrict__ y) {
    float s = 0.0f;
    for (int i = blockIdx.x * blockDim.x + threadIdx.x; i < BSZ * INP;
         i += gridDim.x * blockDim.x) {
        float d = outp[i] - y[i];
        s += d * d;
    }
    s = blockReduceSum(s);
    if (threadIdx.x == 0) atomicAdd(&g_recon, s);
}

__global__ void psl_kernel(const float* __restrict__ h) {
    float s = 0.0f;
    for (int i = blockIdx.x * blockDim.x + threadIdx.x; i < BSZ * HD;
         i += gridDim.x * blockDim.x) {
        float v = h[i];
        s += v * (1.0f - v);
    }
    s = blockReduceSum(s);
    if (threadIdx.x == 0) atomicAdd(&g_psl, s);
}

__global__ void colsum_kernel(const float* __restrict__ h) {
    int col = blockIdx.x * 256 + threadIdx.x;
    int r0 = blockIdx.y * 256;
    if (col >= HD) return;
    float s = 0.0f;
    for (int r = r0; r < r0 + 256; r++) s += h[(size_t)r * HD + col];
    atomicAdd(&g_colsum[col], s);
}

__global__ void finalize_kernel(float* __restrict__ scal) {
    int tid = threadIdx.x;               // 256 threads
    float a = 0.0f;
    for (int c = tid; c < HD; c += 256) {
        float t = g_colsum[c] * (1.0f / BSZ) - RHO_STAR;
        t = fmaxf(t, 0.0f);
        a += t * t;
    }
    a = blockReduceSum(a);
    __shared__ float s_asl;
    if (tid == 0) s_asl = a;
    __syncthreads();
    float l = 0.0f;
    for (int i = tid; i < BSZ * NTOP; i += 256) l += fabsf(g_topy[i] - g_toph[i]);
    l = blockReduceSum(l);
    if (tid == 0) {
        float asl   = s_asl / (float)HD;
        float local = l / (float)(BSZ * NTOP);
        float recon = g_recon / (float)(BSZ * INP);
        float psl   = g_psl / ((float)BSZ * (float)HD);
        scal[0] = recon + psl + asl + local;
        scal[1] = recon;
        scal[2] = psl;
        scal[3] = asl;
        scal[4] = local;
    }
}

// ---------------- launch ----------------
extern "C" void kernel_launch(void* const* d_in, const int* in_sizes, int n_in,
                              void* d_out, int out_size) {
    const float* x  = (const float*)d_in[0];
    const float* y  = (const float*)d_in[1];
    const float* W1 = (const float*)d_in[2];
    const float* b1 = (const float*)d_in[3];
    const float* W2 = (const float*)d_in[4];
    const float* b2 = (const float*)d_in[5];
    float* outp = (float*)d_out;
    float* h    = outp + OFF_H;
    float* scal = outp + OFF_SCAL;

    init_accum_kernel<<<1, 1024>>>();

    // h = clip(x @ W1^T + b1)
    gemm_abt_kernel<1><<<dim3((HD + 127) / 128, BSZ / 128), 256>>>(x, W1, b1, h, BSZ, HD, INP);
    // out = h @ W2^T + b2
    gemm_abt_kernel<0><<<dim3((INP + 127) / 128, BSZ / 128), 256>>>(h, W2, b2, outp, BSZ, INP, HD);

    normalize_y_kernel<<<BSZ, 128>>>(y);
    normalize_h_kernel<<<BSZ, 256>>>(h);

    recon_kernel<<<512, 256>>>(outp, y);
    psl_kernel<<<1024, 256>>>(h);
    colsum_kernel<<<dim3(4, 32), 256>>>(h);

    // My = yn @ yn^T  -> top-10
    symgemm_kernel<YPAD, 0><<<dim3(64, 64), 256>>>();
    topk_kernel<0><<<BSZ, 128>>>();

    // Mh = hn @ hn^T  -> top-10
    symgemm_kernel<HPAD, 1><<<dim3(64, 64), 256>>>();
    topk_kernel<1><<<BSZ, 128>>>();

    finalize_kernel<<<1, 256>>>(scal);
}

// round 3
// speedup vs baseline: 2.3567x; 2.3567x over previous
#include <cuda_runtime.h>
#include <cuda_bf16.h>
#include <math.h>
#include <stdint.h>

#define BSZ   8192
#define INP   300
#define HD    1000
#define YPAD  320      // 300 padded to multiple of 64
#define HPAD  1024     // 1000 padded to multiple of 64
#define NTOP  10
#define RHO_STAR 0.15f

#define OFF_H    (BSZ * INP)            // 2457600
#define OFF_SCAL (OFF_H + BSZ * HD)     // 10649600

// ---------------- static device scratch (no allocations allowed) ----------------
__device__ __align__(16) __nv_bfloat16 g_ynb[BSZ * YPAD];   // normalized y, bf16, zero-padded
__device__ __align__(16) __nv_bfloat16 g_hnb[BSZ * HPAD];   // normalized h, bf16, zero-padded
__device__ __align__(16) float g_M[(size_t)BSZ * BSZ];      // 256 MB similarity matrix scratch
__device__ float g_topy[BSZ * NTOP];
__device__ float g_toph[BSZ * NTOP];
__device__ float g_colsum[HD];
__device__ float g_recon;
__device__ float g_psl;

// ---------------- warp-MMA helpers (base sm_100 ISA: ldmatrix + mma.sync) --------
__device__ __forceinline__ void ldm_x4(uint32_t* r, uint32_t addr) {
    asm volatile("ldmatrix.sync.aligned.m8n8.x4.shared.b16 {%0,%1,%2,%3}, [%4];"
                 : "=r"(r[0]), "=r"(r[1]), "=r"(r[2]), "=r"(r[3]) : "r"(addr));
}
__device__ __forceinline__ void ldm_x2(uint32_t* r, uint32_t addr) {
    asm volatile("ldmatrix.sync.aligned.m8n8.x2.shared.b16 {%0,%1}, [%2];"
                 : "=r"(r[0]), "=r"(r[1]) : "r"(addr));
}
__device__ __forceinline__ void mma16816(float* c, const uint32_t* a, const uint32_t* b) {
    asm volatile(
        "mma.sync.aligned.m16n8k16.row.col.f32.bf16.bf16.f32 "
        "{%0,%1,%2,%3}, {%4,%5,%6,%7}, {%8,%9}, {%0,%1,%2,%3};"
        : "+f"(c[0]), "+f"(c[1]), "+f"(c[2]), "+f"(c[3])
        : "r"(a[0]), "r"(a[1]), "r"(a[2]), "r"(a[3]), "r"(b[0]), "r"(b[1]));
}

// ---------------- generic block reduce ----------------
__device__ __forceinline__ float blockReduceSum(float v) {
    __shared__ float sh[32];
    int lane = threadIdx.x & 31;
    int wid  = threadIdx.x >> 5;
    #pragma unroll
    for (int o = 16; o > 0; o >>= 1) v += __shfl_down_sync(0xffffffffu, v, o);
    if (lane == 0) sh[wid] = v;
    __syncthreads();
    int nw = (blockDim.x + 31) >> 5;
    v = (threadIdx.x < nw) ? sh[lane] : 0.0f;
    if (wid == 0) {
        #pragma unroll
        for (int o = 16; o > 0; o >>= 1) v += __shfl_down_sync(0xffffffffu, v, o);
    }
    return v;
}

// ---------------- init accumulators (runs every replay) ----------------
__global__ void init_accum_kernel() {
    int t = threadIdx.x;
    if (t < HD) g_colsum[t] = 0.0f;
    if (t == HD)     g_recon = 0.0f;
    if (t == HD + 1) g_psl   = 0.0f;
}

// ---------------- row normalization -> bf16 padded ----------------
__global__ void normalize_y_kernel(const float* __restrict__ y) {
    int row = blockIdx.x;
    int t = threadIdx.x;                 // 128 threads
    float s = 0.0f;
    for (int k = t; k < INP; k += 128) { float v = y[row * INP + k]; s += v * v; }
    float tot = blockReduceSum(s);
    __shared__ float snrm;
    if (t == 0) snrm = fmaxf(sqrtf(tot), 1e-6f);
    __syncthreads();
    float inv = 1.0f / snrm;
    for (int k = t; k < YPAD; k += 128)
        g_ynb[(size_t)row * YPAD + k] =
            __float2bfloat16_rn((k < INP) ? y[row * INP + k] * inv : 0.0f);
}

__global__ void normalize_h_kernel(const float* __restrict__ h) {
    int row = blockIdx.x;
    int t = threadIdx.x;                 // 256 threads
    float s = 0.0f;
    for (int k = t; k < HD; k += 256) { float v = h[row * HD + k]; s += v * v; }
    float tot = blockReduceSum(s);
    __shared__ float snrm;
    if (t == 0) snrm = fmaxf(sqrtf(tot), 1e-6f);
    __syncthreads();
    float inv = 1.0f / snrm;
    for (int k = t; k < HPAD; k += 256)
        g_hnb[(size_t)row * HPAD + k] =
            __float2bfloat16_rn((k < HD) ? h[row * HD + k] * inv : 0.0f);
}

// ---------------- generic fp32 C = act(A @ B^T + bias); A:[M,K], B:[N,K] ----------
template <int ACT>   // 0 = none, 1 = clip01
__global__ __launch_bounds__(256, 2)
void gemm_abt_kernel(const float* __restrict__ A, const float* __restrict__ Bm,
                     const float* __restrict__ bias, float* __restrict__ C,
                     int M, int N, int K) {
    __shared__ float As[16][132];
    __shared__ float Bs[16][132];
    int tid = threadIdx.x;
    int tx = tid & 15, ty = tid >> 4;
    int rb = blockIdx.y * 128, cb = blockIdx.x * 128;
    float acc[8][8] = {};
    for (int kk = 0; kk < K; kk += 16) {
        #pragma unroll
        for (int l = 0; l < 8; l++) {
            int e = l * 256 + tid;
            int r = e >> 4, k = e & 15;
            int gk = kk + k;
            int ga = rb + r;
            As[k][r] = (ga < M && gk < K) ? A[(size_t)ga * K + gk] : 0.0f;
            int gb = cb + r;
            Bs[k][r] = (gb < N && gk < K) ? Bm[(size_t)gb * K + gk] : 0.0f;
        }
        __syncthreads();
        #pragma unroll
        for (int k = 0; k < 16; k++) {
            float a[8], b[8];
            #pragma unroll
            for (int i = 0; i < 8; i++) a[i] = As[k][ty * 8 + i];
            #pragma unroll
            for (int j = 0; j < 8; j++) b[j] = Bs[k][tx * 8 + j];
            #pragma unroll
            for (int i = 0; i < 8; i++)
                #pragma unroll
                for (int j = 0; j < 8; j++) acc[i][j] += a[i] * b[j];
        }
        __syncthreads();
    }
    #pragma unroll
    for (int i = 0; i < 8; i++) {
        int gr = rb + ty * 8 + i;
        if (gr >= M) continue;
        #pragma unroll
        for (int j = 0; j < 8; j++) {
            int gc = cb + tx * 8 + j;
            if (gc >= N) continue;
            float v = acc[i][j] + bias[gc];
            if (ACT == 1) v = fminf(fmaxf(v, 0.0f), 1.0f);
            C[(size_t)gr * N + gc] = v;
        }
    }
}

// ---------------- bf16 tensor-core symmetric Gram: g_M = A @ A^T ----------------
// A: [8192, KPAD] bf16 (KPAD % 64 == 0). Upper-triangular 128x128 tiles; writes
// tile and its mirror. 256 threads = 8 warps (warp grid 2x4, warp tile 64x32).
// K processed in 64-wide chunks; smem rows padded to 144B (conflict-free ldmatrix).
#define ASTR 144   // bytes per smem row (64 bf16 data + 8 pad)
template <int KPAD, int WHICH>   // 0 = g_ynb, 1 = g_hnb
__global__ __launch_bounds__(256)
void symgemm_mma_kernel() {
    int bi = blockIdx.y, bj = blockIdx.x;
    if (bi > bj) return;
    __shared__ __align__(16) char smem[2 * 128 * ASTR];     // A tile | B tile (36864 B)
    char* sA = smem;
    char* sB = smem + 128 * ASTR;

    int tid = threadIdx.x, lane = tid & 31, wid = tid >> 5;
    int wm = wid >> 2, wn = wid & 3;                        // warp tile: rows wm*64, cols wn*32
    const __nv_bfloat16* A = WHICH ? g_hnb : g_ynb;
    const char* Arow = (const char*)(A + (size_t)bi * 128 * KPAD);
    const char* Brow = (const char*)(A + (size_t)bj * 128 * KPAD);

    // per-thread ldmatrix base addresses (within-tile byte offsets)
    uint32_t sAu = (uint32_t)__cvta_generic_to_shared(sA);
    uint32_t sBu = (uint32_t)__cvta_generic_to_shared(sB);
    uint32_t aAddr[4], bAddr[4];
    #pragma unroll
    for (int mt = 0; mt < 4; mt++)
        aAddr[mt] = sAu + (wm * 64 + mt * 16 + (lane & 15)) * ASTR + (lane >> 4) * 16;
    #pragma unroll
    for (int nt = 0; nt < 4; nt++)
        bAddr[nt] = sBu + (wn * 32 + nt * 8 + (lane & 7)) * ASTR + ((lane >> 3) & 1) * 16;

    float acc[4][4][4] = {};
    const int NCH = KPAD / 64;
    for (int c = 0; c < NCH; c++) {
        size_t gk = (size_t)c * 128;                        // chunk byte offset in row
        #pragma unroll
        for (int i = 0; i < 4; i++) {                       // 1024 uint4 per tile / 256 thr
            int e = i * 256 + tid;
            int rr = e >> 3, cc = e & 7;
            size_t go = (size_t)rr * (KPAD * 2) + gk + cc * 16;
            int so = rr * ASTR + cc * 16;
            *(uint4*)(sA + so) = *(const uint4*)(Arow + go);
            *(uint4*)(sB + so) = *(const uint4*)(Brow + go);
        }
        __syncthreads();
        #pragma unroll
        for (int ks = 0; ks < 4; ks++) {                    // 4 k-steps of 16 (32B)
            uint32_t af[4][4], bf[4][2];
            #pragma unroll
            for (int mt = 0; mt < 4; mt++) ldm_x4(af[mt], aAddr[mt] + ks * 32);
            #pragma unroll
            for (int nt = 0; nt < 4; nt++) ldm_x2(bf[nt], bAddr[nt] + ks * 32);
            #pragma unroll
            for (int mt = 0; mt < 4; mt++)
                #pragma unroll
                for (int nt = 0; nt < 4; nt++) mma16816(acc[mt][nt], af[mt], bf[nt]);
        }
        __syncthreads();
    }

    // Epilogue: stage 64 rows at a time in smem (reuse tile buffer), then coalesced
    // writes of the tile rows and (if off-diagonal) the mirrored columns.
    float* sbuf = (float*)smem;                             // 64 x 130 fp32 = 33280 B
    const int SSTR = 130;
    size_t rb = (size_t)bi * 128, cb = (size_t)bj * 128;
    int qr = lane >> 2, qc = 2 * (lane & 3);
    #pragma unroll
    for (int p = 0; p < 2; p++) {
        if (wm == p) {
            #pragma unroll
            for (int mt = 0; mt < 4; mt++)
                #pragma unroll
                for (int nt = 0; nt < 4; nt++) {
                    int r0 = mt * 16 + qr;
                    int c0 = wn * 32 + nt * 8 + qc;
                    *(float2*)&sbuf[r0 * SSTR + c0]       = make_float2(acc[mt][nt][0], acc[mt][nt][1]);
                    *(float2*)&sbuf[(r0 + 8) * SSTR + c0] = make_float2(acc[mt][nt][2], acc[mt][nt][3]);
                }
        }
        __syncthreads();
        // tile rows: 256 threads -> 2 rows per iteration
        {
            int cc = tid & 127;
            for (int r = tid >> 7; r < 64; r += 2)
                g_M[(rb + p * 64 + r) * BSZ + cb + cc] = sbuf[r * SSTR + cc];
        }
        if (bi != bj) {
            int r = tid & 63;
            for (int ccol = tid >> 6; ccol < 128; ccol += 4)
                g_M[(cb + ccol) * BSZ + rb + p * 64 + r] = sbuf[r * SSTR + ccol];
        }
        __syncthreads();
    }
}

// ---------------- row-wise top-10 (diag skipped == set to -10) ----------------
template <int WHICH>   // 0 -> g_topy, 1 -> g_toph
__global__ void topk_kernel() {
    int row = blockIdx.x;
    int tid = threadIdx.x;               // 128 threads
    float* outTop = (WHICH == 0) ? g_topy : g_toph;
    const float* Mr = g_M + (size_t)row * BSZ;
    float best[NTOP];
    #pragma unroll
    for (int i = 0; i < NTOP; i++) best[i] = -1e30f;
    for (int j = tid; j < BSZ; j += 128) {
        if (j == row) continue;
        float v = Mr[j];
        if (v > best[NTOP - 1]) {
            best[NTOP - 1] = v;
            #pragma unroll
            for (int i = NTOP - 1; i > 0; --i) {
                if (best[i] > best[i - 1]) {
                    float t = best[i - 1]; best[i - 1] = best[i]; best[i] = t;
                }
            }
        }
    }
    __shared__ float sB[128 * NTOP];
    __shared__ float sV[128];
    __shared__ int   sI[128];
    #pragma unroll
    for (int i = 0; i < NTOP; i++) sB[tid * NTOP + i] = best[i];
    __syncthreads();
    int p = 0;
    for (int r = 0; r < NTOP; r++) {
        sV[tid] = (p < NTOP) ? sB[tid * NTOP + p] : -1e30f;
        sI[tid] = tid;
        __syncthreads();
        for (int s = 64; s > 0; s >>= 1) {
            if (tid < s) {
                if (sV[tid + s] > sV[tid]) { sV[tid] = sV[tid + s]; sI[tid] = sI[tid + s]; }
            }
            __syncthreads();
        }
        if (tid == 0) outTop[row * NTOP + r] = sV[0];
        int w = sI[0];
        if (tid == w) p++;
        __syncthreads();
    }
}

// ---------------- scalar reductions ----------------
__global__ void recon_kernel(const float* __restrict__ outp, const float* __restrict__ y) {
    float s = 0.0f;
    for (int i = blockIdx.x * blockDim.x + threadIdx.x; i < BSZ * INP;
         i += gridDim.x * blockDim.x) {
        float d = outp[i] - y[i];
        s += d * d;
    }
    s = blockReduceSum(s);
    if (threadIdx.x == 0) atomicAdd(&g_recon, s);
}

__global__ void psl_kernel(const float* __restrict__ h) {
    float s = 0.0f;
    for (int i = blockIdx.x * blockDim.x + threadIdx.x; i < BSZ * HD;
         i += gridDim.x * blockDim.x) {
        float v = h[i];
        s += v * (1.0f - v);
    }
    s = blockReduceSum(s);
    if (threadIdx.x == 0) atomicAdd(&g_psl, s);
}

__global__ void colsum_kernel(const float* __restrict__ h) {
    int col = blockIdx.x * 256 + threadIdx.x;
    int r0 = blockIdx.y * 256;
    if (col >= HD) return;
    float s = 0.0f;
    for (int r = r0; r < r0 + 256; r++) s += h[(size_t)r * HD + col];
    atomicAdd(&g_colsum[col], s);
}

__global__ void finalize_kernel(float* __restrict__ scal) {
    int tid = threadIdx.x;               // 256 threads
    float a = 0.0f;
    for (int c = tid; c < HD; c += 256) {
        float t = g_colsum[c] * (1.0f / BSZ) - RHO_STAR;
        t = fmaxf(t, 0.0f);
        a += t * t;
    }
    a = blockReduceSum(a);
    __shared__ float s_asl;
    if (tid == 0) s_asl = a;
    __syncthreads();
    float l = 0.0f;
    for (int i = tid; i < BSZ * NTOP; i += 256) l += fabsf(g_topy[i] - g_toph[i]);
    l = blockReduceSum(l);
    if (tid == 0) {
        float asl   = s_asl / (float)HD;
        float local = l / (float)(BSZ * NTOP);
        float recon = g_recon / (float)(BSZ * INP);
        float psl   = g_psl / ((float)BSZ * (float)HD);
        scal[0] = recon + psl + asl + local;
        scal[1] = recon;
        scal[2] = psl;
        scal[3] = asl;
        scal[4] = local;
    }
}

// ---------------- launch ----------------
extern "C" void kernel_launch(void* const* d_in, const int* in_sizes, int n_in,
                              void* d_out, int out_size) {
    const float* x  = (const float*)d_in[0];
    const float* y  = (const float*)d_in[1];
    const float* W1 = (const float*)d_in[2];
    const float* b1 = (const float*)d_in[3];
    const float* W2 = (const float*)d_in[4];
    const float* b2 = (const float*)d_in[5];
    float* outp = (float*)d_out;
    float* h    = outp + OFF_H;
    float* scal = outp + OFF_SCAL;

    init_accum_kernel<<<1, 1024>>>();

    // h = clip(x @ W1^T + b1), out = h @ W2^T + b2   (fp32-exact path)
    gemm_abt_kernel<1><<<dim3((HD + 127) / 128, BSZ / 128), 256>>>(x, W1, b1, h, BSZ, HD, INP);
    gemm_abt_kernel<0><<<dim3((INP + 127) / 128, BSZ / 128), 256>>>(h, W2, b2, outp, BSZ, INP, HD);

    normalize_y_kernel<<<BSZ, 128>>>(y);
    normalize_h_kernel<<<BSZ, 256>>>(h);

    recon_kernel<<<512, 256>>>(outp, y);
    psl_kernel<<<1024, 256>>>(h);
    colsum_kernel<<<dim3(4, 32), 256>>>(h);

    // My = yn @ yn^T -> top-10
    symgemm_mma_kernel<YPAD, 0><<<dim3(64, 64), 256>>>();
    topk_kernel<0><<<BSZ, 128>>>();

    // Mh = hn @ hn^T -> top-10
    symgemm_mma_kernel<HPAD, 1><<<dim3(64, 64), 256>>>();
    topk_kernel<1><<<BSZ, 128>>>();

    finalize_kernel<<<1, 256>>>(scal);
}

// round 6
// speedup vs baseline: 2.8148x; 1.1944x over previous
#include <cuda_runtime.h>
#include <cuda_bf16.h>
#include <math.h>
#include <stdint.h>

#define BSZ   8192
#define INP   300
#define HD    1000
#define YPAD  320      // 300 padded to 64-multiple
#define HPAD  1024
#define NTOP  10
#define RHO_STAR 0.15f

#define XK3   960      // split-bf16 K for gemm1: 3 * 320
#define HK3   3072     // split-bf16 K for gemm2: 3 * 1024
#define W1R   1024     // W1 rows padded
#define W2R   384      // W2 rows padded

#define OFF_H    (BSZ * INP)
#define OFF_SCAL (OFF_H + BSZ * HD)

// ---------------- static device scratch (footprint identical to round-3 pass) ---
// g_Mbuf serves double duty: during the forward pass its head holds the split-bf16
// operands (X3|W13|H3|W23, 70.4 MB, all dead before symgemm), afterwards it is the
// 8192x8192 fp32 similarity matrix.
__device__ __align__(256) char g_Mbuf[(size_t)BSZ * BSZ * 4];
#define g_M ((float*)g_Mbuf)
#define OFFB_X3   ((size_t)0)
#define OFFB_W13  (OFFB_X3 + (size_t)BSZ * XK3 * 2)         // 15,728,640
#define OFFB_H3   (OFFB_W13 + (size_t)W1R * XK3 * 2)        // 17,694,720
#define OFFB_W23  (OFFB_H3 + (size_t)BSZ * HK3 * 2)         // 68,026,368
__device__ __forceinline__ __nv_bfloat16* P_X3()  { return (__nv_bfloat16*)(g_Mbuf + OFFB_X3); }
__device__ __forceinline__ __nv_bfloat16* P_W13() { return (__nv_bfloat16*)(g_Mbuf + OFFB_W13); }
__device__ __forceinline__ __nv_bfloat16* P_H3()  { return (__nv_bfloat16*)(g_Mbuf + OFFB_H3); }
__device__ __forceinline__ __nv_bfloat16* P_W23() { return (__nv_bfloat16*)(g_Mbuf + OFFB_W23); }

__device__ __align__(16) __nv_bfloat16 g_ynb[BSZ * YPAD];
__device__ __align__(16) __nv_bfloat16 g_hnb[BSZ * HPAD];
__device__ float g_topy[BSZ * NTOP];
__device__ float g_toph[BSZ * NTOP];
__device__ float g_colsum[HD];
__device__ float g_recon;
__device__ float g_psl;

// ---------------- MMA / cp.async helpers (base sm_100 ISA) ----------------
__device__ __forceinline__ void ldm_x4(uint32_t* r, uint32_t addr) {
    asm volatile("ldmatrix.sync.aligned.m8n8.x4.shared.b16 {%0,%1,%2,%3}, [%4];"
                 : "=r"(r[0]), "=r"(r[1]), "=r"(r[2]), "=r"(r[3]) : "r"(addr));
}
__device__ __forceinline__ void ldm_x2(uint32_t* r, uint32_t addr) {
    asm volatile("ldmatrix.sync.aligned.m8n8.x2.shared.b16 {%0,%1}, [%2];"
                 : "=r"(r[0]), "=r"(r[1]) : "r"(addr));
}
__device__ __forceinline__ void mma16816(float* c, const uint32_t* a, const uint32_t* b) {
    asm volatile(
        "mma.sync.aligned.m16n8k16.row.col.f32.bf16.bf16.f32 "
        "{%0,%1,%2,%3}, {%4,%5,%6,%7}, {%8,%9}, {%0,%1,%2,%3};"
        : "+f"(c[0]), "+f"(c[1]), "+f"(c[2]), "+f"(c[3])
        : "r"(a[0]), "r"(a[1]), "r"(a[2]), "r"(a[3]), "r"(b[0]), "r"(b[1]));
}
#define CP_ASYNC16(sm, gp) \
    asm volatile("cp.async.cg.shared.global [%0], [%1], 16;" :: "r"(sm), "l"(gp))
#define CP_COMMIT() asm volatile("cp.async.commit_group;" ::: "memory")
#define CP_WAIT1()  asm volatile("cp.async.wait_group 1;" ::: "memory")
#define CP_WAIT0()  asm volatile("cp.async.wait_group 0;" ::: "memory")

// K-chunk = 32 bf16 = 64 bytes/row; 80-byte padded stride (16B-aligned, conflict-free)
#define ASTR  80
#define TILEB (128 * ASTR)   // 10240
#define STAGE (2 * TILEB)    // A + B per stage = 20480
#define SMEMB (2 * STAGE)    // 40960 static smem, no attribute calls needed

// ---------------- generic block reduce ----------------
__device__ __forceinline__ float blockReduceSum(float v) {
    __shared__ float sh[32];
    int lane = threadIdx.x & 31;
    int wid  = threadIdx.x >> 5;
    #pragma unroll
    for (int o = 16; o > 0; o >>= 1) v += __shfl_down_sync(0xffffffffu, v, o);
    if (lane == 0) sh[wid] = v;
    __syncthreads();
    int nw = (blockDim.x + 31) >> 5;
    v = (threadIdx.x < nw) ? sh[lane] : 0.0f;
    if (wid == 0) {
        #pragma unroll
        for (int o = 16; o > 0; o >>= 1) v += __shfl_down_sync(0xffffffffu, v, o);
    }
    return v;
}

// ---------------- init accumulators ----------------
__global__ void init_accum_kernel() {
    int t = threadIdx.x;
    if (t < HD) g_colsum[t] = 0.0f;
    if (t == HD)     g_recon = 0.0f;
    if (t == HD + 1) g_psl   = 0.0f;
}

// ---------------- split-bf16 conversions ----------------
__global__ void conv_x_kernel(const float* __restrict__ x) {
    __nv_bfloat16* dst = P_X3();
    for (int i = blockIdx.x * 256 + threadIdx.x; i < BSZ * YPAD; i += gridDim.x * 256) {
        int row = i / YPAD, k = i - row * YPAD;
        float v = (k < INP) ? x[row * INP + k] : 0.0f;
        __nv_bfloat16 hi = __float2bfloat16_rn(v);
        __nv_bfloat16 lo = __float2bfloat16_rn(v - __bfloat162float(hi));
        size_t b = (size_t)row * XK3 + k;
        dst[b] = hi; dst[b + YPAD] = hi; dst[b + 2 * YPAD] = lo;
    }
}
__global__ void conv_w1_kernel(const float* __restrict__ W1) {
    __nv_bfloat16* dst = P_W13();
    for (int i = blockIdx.x * 256 + threadIdx.x; i < W1R * YPAD; i += gridDim.x * 256) {
        int row = i / YPAD, k = i - row * YPAD;
        float v = (row < HD && k < INP) ? W1[row * INP + k] : 0.0f;
        __nv_bfloat16 hi = __float2bfloat16_rn(v);
        __nv_bfloat16 lo = __float2bfloat16_rn(v - __bfloat162float(hi));
        size_t b = (size_t)row * XK3 + k;
        dst[b] = hi; dst[b + YPAD] = lo; dst[b + 2 * YPAD] = hi;
    }
}
__global__ void conv_w2_kernel(const float* __restrict__ W2) {
    __nv_bfloat16* dst = P_W23();
    for (int i = blockIdx.x * 256 + threadIdx.x; i < W2R * HPAD; i += gridDim.x * 256) {
        int row = i / HPAD, k = i - row * HPAD;
        float v = (row < INP && k < HD) ? W2[row * HD + k] : 0.0f;
        __nv_bfloat16 hi = __float2bfloat16_rn(v);
        __nv_bfloat16 lo = __float2bfloat16_rn(v - __bfloat162float(hi));
        size_t b = (size_t)row * HK3 + k;
        dst[b] = hi; dst[b + HPAD] = lo; dst[b + 2 * HPAD] = hi;
    }
}

// ---------------- row normalization -> bf16 padded ----------------
__global__ void normalize_y_kernel(const float* __restrict__ y) {
    int row = blockIdx.x;
    int t = threadIdx.x;
    float s = 0.0f;
    for (int k = t; k < INP; k += 128) { float v = y[row * INP + k]; s += v * v; }
    float tot = blockReduceSum(s);
    __shared__ float snrm;
    if (t == 0) snrm = fmaxf(sqrtf(tot), 1e-6f);
    __syncthreads();
    float inv = 1.0f / snrm;
    for (int k = t; k < YPAD; k += 128)
        g_ynb[(size_t)row * YPAD + k] =
            __float2bfloat16_rn((k < INP) ? y[row * INP + k] * inv : 0.0f);
}
__global__ void normalize_h_kernel(const float* __restrict__ h) {
    int row = blockIdx.x;
    int t = threadIdx.x;
    float s = 0.0f;
    for (int k = t; k < HD; k += 256) { float v = h[row * HD + k]; s += v * v; }
    float tot = blockReduceSum(s);
    __shared__ float snrm;
    if (t == 0) snrm = fmaxf(sqrtf(tot), 1e-6f);
    __syncthreads();
    float inv = 1.0f / snrm;
    for (int k = t; k < HPAD; k += 256)
        g_hnb[(size_t)row * HPAD + k] =
            __float2bfloat16_rn((k < HD) ? h[row * HD + k] * inv : 0.0f);
}

// ======== shared warp-MMA mainloop machinery (cp.async 2-stage pipeline) ========
struct MmaCtx {
    uint32_t sbu;
    uint32_t aAddr[4], bAddr[4];
    int tid, lane, wid, wm, wn;
};
__device__ __forceinline__ void mma_init(MmaCtx& cx, char* smem) {
    cx.tid = threadIdx.x; cx.lane = cx.tid & 31; cx.wid = cx.tid >> 5;
    cx.wm = cx.wid >> 2; cx.wn = cx.wid & 3;
    cx.sbu = (uint32_t)__cvta_generic_to_shared(smem);
    #pragma unroll
    for (int mt = 0; mt < 4; mt++)
        cx.aAddr[mt] = cx.sbu + (cx.wm * 64 + mt * 16 + (cx.lane & 15)) * ASTR
                     + (cx.lane >> 4) * 16;
    #pragma unroll
    for (int nt = 0; nt < 4; nt++)
        cx.bAddr[nt] = cx.sbu + TILEB + (cx.wn * 32 + nt * 8 + (cx.lane & 7)) * ASTR
                     + ((cx.lane >> 3) & 1) * 16;
}
template <int KB>   // source bytes per row
__device__ __forceinline__ void issue_chunk(const MmaCtx& cx, const char* Arow,
                                            const char* Brow, int c, int s) {
    size_t gk = (size_t)c * 64;                 // 32 bf16 per chunk
    uint32_t base = cx.sbu + s * STAGE;
    #pragma unroll
    for (int i = 0; i < 2; i++) {               // 512 uint4 per tile / 256 thr
        int e = i * 256 + cx.tid;
        int rr = e >> 2, cc = e & 3;
        size_t go = (size_t)rr * KB + gk + cc * 16;
        uint32_t so = rr * ASTR + cc * 16;
        CP_ASYNC16(base + so, Arow + go);
        CP_ASYNC16(base + TILEB + so, Brow + go);
    }
    CP_COMMIT();
}
__device__ __forceinline__ void compute_chunk(const MmaCtx& cx, int s,
                                              float acc[4][4][4]) {
    uint32_t off = s * STAGE;
    #pragma unroll
    for (int ks = 0; ks < 2; ks++) {            // 2 k-steps of 16
        uint32_t af[4][4], bf[4][2];
        #pragma unroll
        for (int mt = 0; mt < 4; mt++) ldm_x4(af[mt], cx.aAddr[mt] + off + ks * 32);
        #pragma unroll
        for (int nt = 0; nt < 4; nt++) ldm_x2(bf[nt], cx.bAddr[nt] + off + ks * 32);
        #pragma unroll
        for (int mt = 0; mt < 4; mt++)
            #pragma unroll
            for (int nt = 0; nt < 4; nt++) mma16816(acc[mt][nt], af[mt], bf[nt]);
    }
}
#define SSTR 130
__device__ __forceinline__ void stage_acc(const MmaCtx& cx, float* sbuf, int p,
                                          const float acc[4][4][4]) {
    int qr = cx.lane >> 2, qc = 2 * (cx.lane & 3);
    if (cx.wm == p) {
        #pragma unroll
        for (int mt = 0; mt < 4; mt++)
            #pragma unroll
            for (int nt = 0; nt < 4; nt++) {
                int r0 = mt * 16 + qr;
                int c0 = cx.wn * 32 + nt * 8 + qc;
                *(float2*)&sbuf[r0 * SSTR + c0] =
                    make_float2(acc[mt][nt][0], acc[mt][nt][1]);
                *(float2*)&sbuf[(r0 + 8) * SSTR + c0] =
                    make_float2(acc[mt][nt][2], acc[mt][nt][3]);
            }
    }
}

// ---------------- forward GEMM: C = act(A' @ B'^T + bias) ----------------
// AB: 0 = (X3, W13) for gemm1, 1 = (H3, W23) for gemm2.
template <int KP3, int ACT, int WRITE_H3, int AB>
__global__ __launch_bounds__(256)
void gemm_mma_kernel(const float* __restrict__ bias,
                     float* __restrict__ C, int N, int ldc) {
    __shared__ __align__(16) char smem[SMEMB];
    MmaCtx cx; mma_init(cx, smem);
    const __nv_bfloat16* A = (AB == 0) ? P_X3() : P_H3();
    const __nv_bfloat16* B = (AB == 0) ? P_W13() : P_W23();
    const char* Arow = (const char*)(A + (size_t)blockIdx.y * 128 * KP3);
    const char* Brow = (const char*)(B + (size_t)blockIdx.x * 128 * KP3);
    float acc[4][4][4] = {};
    const int NCH = KP3 / 32;
    issue_chunk<KP3 * 2>(cx, Arow, Brow, 0, 0);
    for (int c = 0; c < NCH; c++) {
        int s = c & 1;
        if (c + 1 < NCH) { issue_chunk<KP3 * 2>(cx, Arow, Brow, c + 1, s ^ 1); CP_WAIT1(); }
        else CP_WAIT0();
        __syncthreads();
        compute_chunk(cx, s, acc);
        __syncthreads();
    }
    float* sbuf = (float*)smem;
    size_t rb = (size_t)blockIdx.y * 128, cb = (size_t)blockIdx.x * 128;
    __nv_bfloat16* h3 = P_H3();
    #pragma unroll
    for (int p = 0; p < 2; p++) {
        stage_acc(cx, sbuf, p, acc);
        __syncthreads();
        int cc = cx.tid & 127;
        int gc = (int)cb + cc;
        for (int r = cx.tid >> 7; r < 64; r += 2) {
            size_t gr = rb + p * 64 + r;
            float v = 0.0f;
            if (gc < N) {
                v = sbuf[r * SSTR + cc] + bias[gc];
                if (ACT == 1) v = fminf(fmaxf(v, 0.0f), 1.0f);
                C[gr * ldc + gc] = v;
            }
            if (WRITE_H3) {
                __nv_bfloat16 hi = __float2bfloat16_rn(v);
                __nv_bfloat16 lo = __float2bfloat16_rn(v - __bfloat162float(hi));
                size_t b = gr * HK3 + gc;
                h3[b] = hi; h3[b + HPAD] = hi; h3[b + 2 * HPAD] = lo;
            }
        }
        __syncthreads();
    }
}

// ---------------- symmetric Gram: g_M = A @ A^T (triangular + mirror) ----------
template <int KPAD, int WHICH>
__global__ __launch_bounds__(256)
void symgemm_mma_kernel() {
    int bi = blockIdx.y, bj = blockIdx.x;
    if (bi > bj) return;
    __shared__ __align__(16) char smem[SMEMB];
    MmaCtx cx; mma_init(cx, smem);
    const __nv_bfloat16* A = WHICH ? g_hnb : g_ynb;
    const char* Arow = (const char*)(A + (size_t)bi * 128 * KPAD);
    const char* Brow = (const char*)(A + (size_t)bj * 128 * KPAD);
    float acc[4][4][4] = {};
    const int NCH = KPAD / 32;
    issue_chunk<KPAD * 2>(cx, Arow, Brow, 0, 0);
    for (int c = 0; c < NCH; c++) {
        int s = c & 1;
        if (c + 1 < NCH) { issue_chunk<KPAD * 2>(cx, Arow, Brow, c + 1, s ^ 1); CP_WAIT1(); }
        else CP_WAIT0();
        __syncthreads();
        compute_chunk(cx, s, acc);
        __syncthreads();
    }
    float* sbuf = (float*)smem;
    size_t rb = (size_t)bi * 128, cb = (size_t)bj * 128;
    #pragma unroll
    for (int p = 0; p < 2; p++) {
        stage_acc(cx, sbuf, p, acc);
        __syncthreads();
        {
            int cc = cx.tid & 127;
            for (int r = cx.tid >> 7; r < 64; r += 2)
                g_M[(rb + p * 64 + r) * BSZ + cb + cc] = sbuf[r * SSTR + cc];
        }
        if (bi != bj) {
            int r = cx.tid & 63;
            for (int ccol = cx.tid >> 6; ccol < 128; ccol += 4)
                g_M[(cb + ccol) * BSZ + rb + p * 64 + r] = sbuf[r * SSTR + ccol];
        }
        __syncthreads();
    }
}

// ---------------- row-wise top-10 ----------------
template <int WHICH>
__global__ void topk_kernel() {
    int row = blockIdx.x;
    int tid = threadIdx.x;               // 128 threads
    float* outTop = (WHICH == 0) ? g_topy : g_toph;
    const float* Mr = g_M + (size_t)row * BSZ;
    float best[NTOP];
    #pragma unroll
    for (int i = 0; i < NTOP; i++) best[i] = -1e30f;
    for (int j = tid; j < BSZ; j += 128) {
        if (j == row) continue;
        float v = Mr[j];
        if (v > best[NTOP - 1]) {
            best[NTOP - 1] = v;
            #pragma unroll
            for (int i = NTOP - 1; i > 0; --i) {
                if (best[i] > best[i - 1]) {
                    float t = best[i - 1]; best[i - 1] = best[i]; best[i] = t;
                }
            }
        }
    }
    __shared__ float sB[128 * NTOP];
    __shared__ float sV[128];
    __shared__ int   sI[128];
    #pragma unroll
    for (int i = 0; i < NTOP; i++) sB[tid * NTOP + i] = best[i];
    __syncthreads();
    int p = 0;
    for (int r = 0; r < NTOP; r++) {
        sV[tid] = (p < NTOP) ? sB[tid * NTOP + p] : -1e30f;
        sI[tid] = tid;
        __syncthreads();
        for (int s = 64; s > 0; s >>= 1) {
            if (tid < s) {
                if (sV[tid + s] > sV[tid]) { sV[tid] = sV[tid + s]; sI[tid] = sI[tid + s]; }
            }
            __syncthreads();
        }
        if (tid == 0) outTop[row * NTOP + r] = sV[0];
        int w = sI[0];
        if (tid == w) p++;
        __syncthreads();
    }
}

// ---------------- scalar reductions ----------------
__global__ void recon_kernel(const float* __restrict__ outp, const float* __restrict__ y) {
    float s = 0.0f;
    for (int i = blockIdx.x * blockDim.x + threadIdx.x; i < BSZ * INP;
         i += gridDim.x * blockDim.x) {
        float d = outp[i] - y[i];
        s += d * d;
    }
    s = blockReduceSum(s);
    if (threadIdx.x == 0) atomicAdd(&g_recon, s);
}
__global__ void psl_kernel(const float* __restrict__ h) {
    float s = 0.0f;
    for (int i = blockIdx.x * blockDim.x + threadIdx.x; i < BSZ * HD;
         i += gridDim.x * blockDim.x) {
        float v = h[i];
        s += v * (1.0f - v);
    }
    s = blockReduceSum(s);
    if (threadIdx.x == 0) atomicAdd(&g_psl, s);
}
__global__ void colsum_kernel(const float* __restrict__ h) {
    int col = blockIdx.x * 256 + threadIdx.x;
    int r0 = blockIdx.y * 256;
    if (col >= HD) return;
    float s = 0.0f;
    for (int r = r0; r < r0 + 256; r++) s += h[(size_t)r * HD + col];
    atomicAdd(&g_colsum[col], s);
}
__global__ void finalize_kernel(float* __restrict__ scal) {
    int tid = threadIdx.x;               // 256 threads
    float a = 0.0f;
    for (int c = tid; c < HD; c += 256) {
        float t = g_colsum[c] * (1.0f / BSZ) - RHO_STAR;
        t = fmaxf(t, 0.0f);
        a += t * t;
    }
    a = blockReduceSum(a);
    __shared__ float s_asl;
    if (tid == 0) s_asl = a;
    __syncthreads();
    float l = 0.0f;
    for (int i = tid; i < BSZ * NTOP; i += 256) l += fabsf(g_topy[i] - g_toph[i]);
    l = blockReduceSum(l);
    if (tid == 0) {
        float asl   = s_asl / (float)HD;
        float local = l / (float)(BSZ * NTOP);
        float recon = g_recon / (float)(BSZ * INP);
        float psl   = g_psl / ((float)BSZ * (float)HD);
        scal[0] = recon + psl + asl + local;
        scal[1] = recon;
        scal[2] = psl;
        scal[3] = asl;
        scal[4] = local;
    }
}

// ---------------- launch ----------------
extern "C" void kernel_launch(void* const* d_in, const int* in_sizes, int n_in,
                              void* d_out, int out_size) {
    const float* x  = (const float*)d_in[0];
    const float* y  = (const float*)d_in[1];
    const float* W1 = (const float*)d_in[2];
    const float* b1 = (const float*)d_in[3];
    const float* W2 = (const float*)d_in[4];
    const float* b2 = (const float*)d_in[5];
    float* outp = (float*)d_out;
    float* h    = outp + OFF_H;
    float* scal = outp + OFF_SCAL;

    init_accum_kernel<<<1, 1024>>>();
    conv_x_kernel<<<512, 256>>>(x);
    conv_w1_kernel<<<256, 256>>>(W1);
    conv_w2_kernel<<<256, 256>>>(W2);

    // h = clip(x@W1^T + b1)  (split-bf16, fp32-grade); also emits H3
    gemm_mma_kernel<XK3, 1, 1, 0><<<dim3(8, 64), 256>>>(b1, h, HD, HD);
    // out = h@W2^T + b2
    gemm_mma_kernel<HK3, 0, 0, 1><<<dim3(3, 64), 256>>>(b2, outp, INP, INP);

    normalize_y_kernel<<<BSZ, 128>>>(y);
    normalize_h_kernel<<<BSZ, 256>>>(h);

    recon_kernel<<<512, 256>>>(outp, y);
    psl_kernel<<<1024, 256>>>(h);
    colsum_kernel<<<dim3(4, 32), 256>>>(h);

    // My = yn@yn^T -> top-10   (first writer of g_M; split buffers are dead now)
    symgemm_mma_kernel<YPAD, 0><<<dim3(64, 64), 256>>>();
    topk_kernel<0><<<BSZ, 128>>>();
    // Mh = hn@hn^T -> top-10
    symgemm_mma_kernel<HPAD, 1><<<dim3(64, 64), 256>>>();
    topk_kernel<1><<<BSZ, 128>>>();

    finalize_kernel<<<1, 256>>>(scal);
}

// round 7
// speedup vs baseline: 2.9688x; 1.0547x over previous
#include <cuda_runtime.h>
#include <cuda_bf16.h>
#include <math.h>
#include <stdint.h>

#define BSZ   8192
#define INP   300
#define HD    1000
#define YPAD  320      // 300 padded to 64-multiple
#define HPAD  1024
#define NTOP  10
#define RHO_STAR 0.15f

#define XK3   960      // split-bf16 K for gemm1: 3 * 320
#define HK3   3072     // split-bf16 K for gemm2: 3 * 1024
#define W1R   1024
#define W2R   384

#define OFF_H    (BSZ * INP)
#define OFF_SCAL (OFF_H + BSZ * HD)

// ---------------- static device scratch (same footprint as passing R6) ----------
// g_Mbuf phases: [conv/gemm phase] split-bf16 operands X3|W13|H3|W23 (70.4 MB)
//               [gram phase]      per-row top-10 partials part[8192][64][10] (21 MB)
__device__ __align__(256) char g_Mbuf[(size_t)BSZ * BSZ * 4];
#define OFFB_X3   ((size_t)0)
#define OFFB_W13  (OFFB_X3 + (size_t)BSZ * XK3 * 2)
#define OFFB_H3   (OFFB_W13 + (size_t)W1R * XK3 * 2)
#define OFFB_W23  (OFFB_H3 + (size_t)BSZ * HK3 * 2)
__device__ __forceinline__ __nv_bfloat16* P_X3()  { return (__nv_bfloat16*)(g_Mbuf + OFFB_X3); }
__device__ __forceinline__ __nv_bfloat16* P_W13() { return (__nv_bfloat16*)(g_Mbuf + OFFB_W13); }
__device__ __forceinline__ __nv_bfloat16* P_H3()  { return (__nv_bfloat16*)(g_Mbuf + OFFB_H3); }
__device__ __forceinline__ __nv_bfloat16* P_W23() { return (__nv_bfloat16*)(g_Mbuf + OFFB_W23); }
__device__ __forceinline__ float* P_PART() { return (float*)g_Mbuf; }   // 8192*640 floats

__device__ __align__(16) __nv_bfloat16 g_ynb[BSZ * YPAD];
__device__ __align__(16) __nv_bfloat16 g_hnb[BSZ * HPAD];
__device__ float g_topy[BSZ * NTOP];
__device__ float g_toph[BSZ * NTOP];
__device__ float g_colsum[HD];
__device__ float g_recon;
__device__ float g_psl;

// ---------------- MMA / cp.async helpers (base sm_100 ISA) ----------------
__device__ __forceinline__ void ldm_x4(uint32_t* r, uint32_t addr) {
    asm volatile("ldmatrix.sync.aligned.m8n8.x4.shared.b16 {%0,%1,%2,%3}, [%4];"
                 : "=r"(r[0]), "=r"(r[1]), "=r"(r[2]), "=r"(r[3]) : "r"(addr));
}
__device__ __forceinline__ void ldm_x2(uint32_t* r, uint32_t addr) {
    asm volatile("ldmatrix.sync.aligned.m8n8.x2.shared.b16 {%0,%1}, [%2];"
                 : "=r"(r[0]), "=r"(r[1]) : "r"(addr));
}
__device__ __forceinline__ void mma16816(float* c, const uint32_t* a, const uint32_t* b) {
    asm volatile(
        "mma.sync.aligned.m16n8k16.row.col.f32.bf16.bf16.f32 "
        "{%0,%1,%2,%3}, {%4,%5,%6,%7}, {%8,%9}, {%0,%1,%2,%3};"
        : "+f"(c[0]), "+f"(c[1]), "+f"(c[2]), "+f"(c[3])
        : "r"(a[0]), "r"(a[1]), "r"(a[2]), "r"(a[3]), "r"(b[0]), "r"(b[1]));
}
#define CP_ASYNC16(sm, gp) \
    asm volatile("cp.async.cg.shared.global [%0], [%1], 16;" :: "r"(sm), "l"(gp))
#define CP_COMMIT() asm volatile("cp.async.commit_group;" ::: "memory")
#define CP_WAIT1()  asm volatile("cp.async.wait_group 1;" ::: "memory")
#define CP_WAIT0()  asm volatile("cp.async.wait_group 0;" ::: "memory")

#define ASTR  80
#define TILEB (128 * ASTR)   // 10240
#define STAGE (2 * TILEB)    // 20480
#define SMEMB (2 * STAGE)    // 40960 static smem

// ---------------- top-10 register helpers (constant-indexed -> registers) -------
__device__ __forceinline__ void ins10(float* b, float v) {
    if (v > b[NTOP - 1]) {
        b[NTOP - 1] = v;
        #pragma unroll
        for (int i = NTOP - 1; i > 0; --i)
            if (b[i] > b[i - 1]) { float t = b[i - 1]; b[i - 1] = b[i]; b[i] = t; }
    }
}
__device__ __forceinline__ void merge_shfl(float* b, int xorm) {
    float o[NTOP];
    #pragma unroll
    for (int j = 0; j < NTOP; j++) o[j] = __shfl_xor_sync(0xffffffffu, b[j], xorm);
    #pragma unroll
    for (int j = 0; j < NTOP; j++) ins10(b, o[j]);
}

// ---------------- generic block reduce ----------------
__device__ __forceinline__ float blockReduceSum(float v) {
    __shared__ float sh[32];
    int lane = threadIdx.x & 31;
    int wid  = threadIdx.x >> 5;
    #pragma unroll
    for (int o = 16; o > 0; o >>= 1) v += __shfl_down_sync(0xffffffffu, v, o);
    if (lane == 0) sh[wid] = v;
    __syncthreads();
    int nw = (blockDim.x + 31) >> 5;
    v = (threadIdx.x < nw) ? sh[lane] : 0.0f;
    if (wid == 0) {
        #pragma unroll
        for (int o = 16; o > 0; o >>= 1) v += __shfl_down_sync(0xffffffffu, v, o);
    }
    return v;
}

// ---------------- init accumulators ----------------
__global__ void init_accum_kernel() {
    int t = threadIdx.x;
    if (t < HD) g_colsum[t] = 0.0f;
    if (t == HD)     g_recon = 0.0f;
    if (t == HD + 1) g_psl   = 0.0f;
}

// ---------------- split-bf16 conversions ----------------
__global__ void conv_x_kernel(const float* __restrict__ x) {
    __nv_bfloat16* dst = P_X3();
    for (int i = blockIdx.x * 256 + threadIdx.x; i < BSZ * YPAD; i += gridDim.x * 256) {
        int row = i / YPAD, k = i - row * YPAD;
        float v = (k < INP) ? x[row * INP + k] : 0.0f;
        __nv_bfloat16 hi = __float2bfloat16_rn(v);
        __nv_bfloat16 lo = __float2bfloat16_rn(v - __bfloat162float(hi));
        size_t b = (size_t)row * XK3 + k;
        dst[b] = hi; dst[b + YPAD] = hi; dst[b + 2 * YPAD] = lo;
    }
}
__global__ void conv_w1_kernel(const float* __restrict__ W1) {
    __nv_bfloat16* dst = P_W13();
    for (int i = blockIdx.x * 256 + threadIdx.x; i < W1R * YPAD; i += gridDim.x * 256) {
        int row = i / YPAD, k = i - row * YPAD;
        float v = (row < HD && k < INP) ? W1[row * INP + k] : 0.0f;
        __nv_bfloat16 hi = __float2bfloat16_rn(v);
        __nv_bfloat16 lo = __float2bfloat16_rn(v - __bfloat162float(hi));
        size_t b = (size_t)row * XK3 + k;
        dst[b] = hi; dst[b + YPAD] = lo; dst[b + 2 * YPAD] = hi;
    }
}
__global__ void conv_w2_kernel(const float* __restrict__ W2) {
    __nv_bfloat16* dst = P_W23();
    for (int i = blockIdx.x * 256 + threadIdx.x; i < W2R * HPAD; i += gridDim.x * 256) {
        int row = i / HPAD, k = i - row * HPAD;
        float v = (row < INP && k < HD) ? W2[row * HD + k] : 0.0f;
        __nv_bfloat16 hi = __float2bfloat16_rn(v);
        __nv_bfloat16 lo = __float2bfloat16_rn(v - __bfloat162float(hi));
        size_t b = (size_t)row * HK3 + k;
        dst[b] = hi; dst[b + HPAD] = lo; dst[b + 2 * HPAD] = hi;
    }
}

// ---------------- row normalization -> bf16 padded ----------------
__global__ void normalize_y_kernel(const float* __restrict__ y) {
    int row = blockIdx.x;
    int t = threadIdx.x;
    float s = 0.0f;
    for (int k = t; k < INP; k += 128) { float v = y[row * INP + k]; s += v * v; }
    float tot = blockReduceSum(s);
    __shared__ float snrm;
    if (t == 0) snrm = fmaxf(sqrtf(tot), 1e-6f);
    __syncthreads();
    float inv = 1.0f / snrm;
    for (int k = t; k < YPAD; k += 128)
        g_ynb[(size_t)row * YPAD + k] =
            __float2bfloat16_rn((k < INP) ? y[row * INP + k] * inv : 0.0f);
}
__global__ void normalize_h_kernel(const float* __restrict__ h) {
    int row = blockIdx.x;
    int t = threadIdx.x;
    float s = 0.0f;
    for (int k = t; k < HD; k += 256) { float v = h[row * HD + k]; s += v * v; }
    float tot = blockReduceSum(s);
    __shared__ float snrm;
    if (t == 0) snrm = fmaxf(sqrtf(tot), 1e-6f);
    __syncthreads();
    float inv = 1.0f / snrm;
    for (int k = t; k < HPAD; k += 256)
        g_hnb[(size_t)row * HPAD + k] =
            __float2bfloat16_rn((k < HD) ? h[row * HD + k] * inv : 0.0f);
}

// ======== shared warp-MMA mainloop machinery (cp.async 2-stage pipeline) ========
struct MmaCtx {
    uint32_t sbu;
    uint32_t aAddr[4], bAddr[4];
    int tid, lane, wid, wm, wn;
};
__device__ __forceinline__ void mma_init(MmaCtx& cx, char* smem) {
    cx.tid = threadIdx.x; cx.lane = cx.tid & 31; cx.wid = cx.tid >> 5;
    cx.wm = cx.wid >> 2; cx.wn = cx.wid & 3;
    cx.sbu = (uint32_t)__cvta_generic_to_shared(smem);
    #pragma unroll
    for (int mt = 0; mt < 4; mt++)
        cx.aAddr[mt] = cx.sbu + (cx.wm * 64 + mt * 16 + (cx.lane & 15)) * ASTR
                     + (cx.lane >> 4) * 16;
    #pragma unroll
    for (int nt = 0; nt < 4; nt++)
        cx.bAddr[nt] = cx.sbu + TILEB + (cx.wn * 32 + nt * 8 + (cx.lane & 7)) * ASTR
                     + ((cx.lane >> 3) & 1) * 16;
}
template <int KB>
__device__ __forceinline__ void issue_chunk(const MmaCtx& cx, const char* Arow,
                                            const char* Brow, int c, int s) {
    size_t gk = (size_t)c * 64;
    uint32_t base = cx.sbu + s * STAGE;
    #pragma unroll
    for (int i = 0; i < 2; i++) {
        int e = i * 256 + cx.tid;
        int rr = e >> 2, cc = e & 3;
        size_t go = (size_t)rr * KB + gk + cc * 16;
        uint32_t so = rr * ASTR + cc * 16;
        CP_ASYNC16(base + so, Arow + go);
        CP_ASYNC16(base + TILEB + so, Brow + go);
    }
    CP_COMMIT();
}
__device__ __forceinline__ void compute_chunk(const MmaCtx& cx, int s,
                                              float acc[4][4][4]) {
    uint32_t off = s * STAGE;
    #pragma unroll
    for (int ks = 0; ks < 2; ks++) {
        uint32_t af[4][4], bf[4][2];
        #pragma unroll
        for (int mt = 0; mt < 4; mt++) ldm_x4(af[mt], cx.aAddr[mt] + off + ks * 32);
        #pragma unroll
        for (int nt = 0; nt < 4; nt++) ldm_x2(bf[nt], cx.bAddr[nt] + off + ks * 32);
        #pragma unroll
        for (int mt = 0; mt < 4; mt++)
            #pragma unroll
            for (int nt = 0; nt < 4; nt++) mma16816(acc[mt][nt], af[mt], bf[nt]);
    }
}
#define SSTR 130
__device__ __forceinline__ void stage_acc(const MmaCtx& cx, float* sbuf, int p,
                                          const float acc[4][4][4]) {
    int qr = cx.lane >> 2, qc = 2 * (cx.lane & 3);
    if (cx.wm == p) {
        #pragma unroll
        for (int mt = 0; mt < 4; mt++)
            #pragma unroll
            for (int nt = 0; nt < 4; nt++) {
                int r0 = mt * 16 + qr;
                int c0 = cx.wn * 32 + nt * 8 + qc;
                *(float2*)&sbuf[r0 * SSTR + c0] =
                    make_float2(acc[mt][nt][0], acc[mt][nt][1]);
                *(float2*)&sbuf[(r0 + 8) * SSTR + c0] =
                    make_float2(acc[mt][nt][2], acc[mt][nt][3]);
            }
    }
}

// ---------------- forward GEMM: C = act(A' @ B'^T + bias) ----------------
template <int KP3, int ACT, int WRITE_H3, int AB>
__global__ __launch_bounds__(256)
void gemm_mma_kernel(const float* __restrict__ bias,
                     float* __restrict__ C, int N, int ldc) {
    __shared__ __align__(16) char smem[SMEMB];
    MmaCtx cx; mma_init(cx, smem);
    const __nv_bfloat16* A = (AB == 0) ? P_X3() : P_H3();
    const __nv_bfloat16* B = (AB == 0) ? P_W13() : P_W23();
    const char* Arow = (const char*)(A + (size_t)blockIdx.y * 128 * KP3);
    const char* Brow = (const char*)(B + (size_t)blockIdx.x * 128 * KP3);
    float acc[4][4][4] = {};
    const int NCH = KP3 / 32;
    issue_chunk<KP3 * 2>(cx, Arow, Brow, 0, 0);
    for (int c = 0; c < NCH; c++) {
        int s = c & 1;
        if (c + 1 < NCH) { issue_chunk<KP3 * 2>(cx, Arow, Brow, c + 1, s ^ 1); CP_WAIT1(); }
        else CP_WAIT0();
        __syncthreads();
        compute_chunk(cx, s, acc);
        __syncthreads();
    }
    float* sbuf = (float*)smem;
    size_t rb = (size_t)blockIdx.y * 128, cb = (size_t)blockIdx.x * 128;
    __nv_bfloat16* h3 = P_H3();
    #pragma unroll
    for (int p = 0; p < 2; p++) {
        stage_acc(cx, sbuf, p, acc);
        __syncthreads();
        int cc = cx.tid & 127;
        int gc = (int)cb + cc;
        for (int r = cx.tid >> 7; r < 64; r += 2) {
            size_t gr = rb + p * 64 + r;
            float v = 0.0f;
            if (gc < N) {
                v = sbuf[r * SSTR + cc] + bias[gc];
                if (ACT == 1) v = fminf(fmaxf(v, 0.0f), 1.0f);
                C[gr * ldc + gc] = v;
            }
            if (WRITE_H3) {
                __nv_bfloat16 hi = __float2bfloat16_rn(v);
                __nv_bfloat16 lo = __float2bfloat16_rn(v - __bfloat162float(hi));
                size_t b = gr * HK3 + gc;
                h3[b] = hi; h3[b + HPAD] = hi; h3[b + 2 * HPAD] = lo;
            }
        }
        __syncthreads();
    }
}

// ---------------- fused symmetric Gram + per-tile top-10 partials ----------------
// part[row][j][10]: top-10 of M[row, 128j .. 128j+127] (diag excluded), written
// exactly once: row-scan covers slots j >= i, mirror-scan covers slots j < i.
template <int KPAD, int WHICH>
__global__ __launch_bounds__(256)
void symgemm_topk_kernel() {
    int bi = blockIdx.y, bj = blockIdx.x;
    if (bi > bj) return;
    __shared__ __align__(16) char smem[SMEMB];
    MmaCtx cx; mma_init(cx, smem);
    const __nv_bfloat16* A = WHICH ? g_hnb : g_ynb;
    const char* Arow = (const char*)(A + (size_t)bi * 128 * KPAD);
    const char* Brow = (const char*)(A + (size_t)bj * 128 * KPAD);
    float acc[4][4][4] = {};
    const int NCH = KPAD / 32;
    issue_chunk<KPAD * 2>(cx, Arow, Brow, 0, 0);
    for (int c = 0; c < NCH; c++) {
        int s = c & 1;
        if (c + 1 < NCH) { issue_chunk<KPAD * 2>(cx, Arow, Brow, c + 1, s ^ 1); CP_WAIT1(); }
        else CP_WAIT0();
        __syncthreads();
        compute_chunk(cx, s, acc);
        __syncthreads();
    }
    float* sbuf = (float*)smem;
    float* part = P_PART();
    int rb = bi * 128, cb = bj * 128;
    bool diag = (bi == bj);

    // mirror (column) tops accumulate across both p halves
    float ct[NTOP];
    #pragma unroll
    for (int k = 0; k < NTOP; k++) ct[k] = -1e30f;
    int mcol = cx.tid >> 1, mseg = cx.tid & 1;

    #pragma unroll
    for (int p = 0; p < 2; p++) {
        stage_acc(cx, sbuf, p, acc);
        __syncthreads();
        // row tops: 128 threads (warps 0-3), 2 per row, 64 cols each
        if (cx.tid < 128) {
            int row = cx.tid >> 1, seg = cx.tid & 1;
            int gr = rb + p * 64 + row;
            float bt[NTOP];
            #pragma unroll
            for (int k = 0; k < NTOP; k++) bt[k] = -1e30f;
            const float* sr = &sbuf[row * SSTR + seg * 64];
            int gc0 = cb + seg * 64;
            for (int c = 0; c < 64; c++) {
                float v = sr[c];
                if (!diag || (gc0 + c) != gr) ins10(bt, v);
            }
            merge_shfl(bt, 1);
            if (seg == 0) {
                float* dst = part + ((size_t)gr * 64 + bj) * NTOP;
                #pragma unroll
                for (int k = 0; k < NTOP; k++) dst[k] = bt[k];
            }
        }
        // mirror tops: all 256 threads, 2 per column, 32 rows each
        if (!diag) {
            const float* sc = &sbuf[(mseg * 32) * SSTR + mcol];
            for (int r = 0; r < 32; r++) ins10(ct, sc[r * SSTR]);
        }
        __syncthreads();
    }
    if (!diag) {
        merge_shfl(ct, 1);
        if (mseg == 0) {
            float* dst = part + ((size_t)(cb + mcol) * 64 + bi) * NTOP;
            #pragma unroll
            for (int k = 0; k < NTOP; k++) dst[k] = ct[k];
        }
    }
}

// ---------------- merge 64 sorted partials -> global top-10 per row -------------
template <int WHICH>
__global__ void merge_topk_kernel() {
    int row = blockIdx.x;
    int tid = threadIdx.x;               // 64 threads, one partial slot each
    float* outTop = (WHICH == 0) ? g_topy : g_toph;
    const float* src = P_PART() + ((size_t)row * 64 + tid) * NTOP;
    __shared__ float sB[64 * NTOP];
    __shared__ float sV[64];
    __shared__ int   sI[64];
    #pragma unroll
    for (int k = 0; k < NTOP; k++) sB[tid * NTOP + k] = src[k];
    __syncthreads();
    int p = 0;
    for (int r = 0; r < NTOP; r++) {
        sV[tid] = (p < NTOP) ? sB[tid * NTOP + p] : -1e30f;
        sI[tid] = tid;
        __syncthreads();
        for (int s = 32; s > 0; s >>= 1) {
            if (tid < s) {
                if (sV[tid + s] > sV[tid]) { sV[tid] = sV[tid + s]; sI[tid] = sI[tid + s]; }
            }
            __syncthreads();
        }
        if (tid == 0) outTop[row * NTOP + r] = sV[0];
        int w = sI[0];
        if (tid == w) p++;
        __syncthreads();
    }
}

// ---------------- scalar reductions ----------------
__global__ void recon_kernel(const float* __restrict__ outp, const float* __restrict__ y) {
    float s = 0.0f;
    for (int i = blockIdx.x * blockDim.x + threadIdx.x; i < BSZ * INP;
         i += gridDim.x * blockDim.x) {
        float d = outp[i] - y[i];
        s += d * d;
    }
    s = blockReduceSum(s);
    if (threadIdx.x == 0) atomicAdd(&g_recon, s);
}
// colsum + psl fused (single pass over h)
__global__ void colsum_psl_kernel(const float* __restrict__ h) {
    int col = blockIdx.x * 256 + threadIdx.x;
    int r0 = blockIdx.y * 256;
    float s = 0.0f, ps = 0.0f;
    if (col < HD) {
        for (int r = r0; r < r0 + 256; r++) {
            float v = h[(size_t)r * HD + col];
            s += v;
            ps += v * (1.0f - v);
        }
        atomicAdd(&g_colsum[col], s);
    }
    ps = blockReduceSum(ps);
    if (threadIdx.x == 0) atomicAdd(&g_psl, ps);
}
__global__ void finalize_kernel(float* __restrict__ scal) {
    int tid = threadIdx.x;               // 256 threads
    float a = 0.0f;
    for (int c = tid; c < HD; c += 256) {
        float t = g_colsum[c] * (1.0f / BSZ) - RHO_STAR;
        t = fmaxf(t, 0.0f);
        a += t * t;
    }
    a = blockReduceSum(a);
    __shared__ float s_asl;
    if (tid == 0) s_asl = a;
    __syncthreads();
    float l = 0.0f;
    for (int i = tid; i < BSZ * NTOP; i += 256) l += fabsf(g_topy[i] - g_toph[i]);
    l = blockReduceSum(l);
    if (tid == 0) {
        float asl   = s_asl / (float)HD;
        float local = l / (float)(BSZ * NTOP);
        float recon = g_recon / (float)(BSZ * INP);
        float psl   = g_psl / ((float)BSZ * (float)HD);
        scal[0] = recon + psl + asl + local;
        scal[1] = recon;
        scal[2] = psl;
        scal[3] = asl;
        scal[4] = local;
    }
}

// ---------------- launch ----------------
extern "C" void kernel_launch(void* const* d_in, const int* in_sizes, int n_in,
                              void* d_out, int out_size) {
    const float* x  = (const float*)d_in[0];
    const float* y  = (const float*)d_in[1];
    const float* W1 = (const float*)d_in[2];
    const float* b1 = (const float*)d_in[3];
    const float* W2 = (const float*)d_in[4];
    const float* b2 = (const float*)d_in[5];
    float* outp = (float*)d_out;
    float* h    = outp + OFF_H;
    float* scal = outp + OFF_SCAL;

    init_accum_kernel<<<1, 1024>>>();
    conv_x_kernel<<<512, 256>>>(x);
    conv_w1_kernel<<<256, 256>>>(W1);
    conv_w2_kernel<<<256, 256>>>(W2);

    // h = clip(x@W1^T + b1)  (split-bf16, fp32-grade); also emits H3
    gemm_mma_kernel<XK3, 1, 1, 0><<<dim3(8, 64), 256>>>(b1, h, HD, HD);
    // out = h@W2^T + b2
    gemm_mma_kernel<HK3, 0, 0, 1><<<dim3(3, 64), 256>>>(b2, outp, INP, INP);

    normalize_y_kernel<<<BSZ, 128>>>(y);
    normalize_h_kernel<<<BSZ, 256>>>(h);

    recon_kernel<<<512, 256>>>(outp, y);
    colsum_psl_kernel<<<dim3(4, 32), 256>>>(h);

    // My = yn@yn^T -> fused per-tile top-10 partials -> merge
    symgemm_topk_kernel<YPAD, 0><<<dim3(64, 64), 256>>>();
    merge_topk_kernel<0><<<BSZ, 64>>>();
    // Mh = hn@hn^T -> fused per-tile top-10 partials -> merge
    symgemm_topk_kernel<HPAD, 1><<<dim3(64, 64), 256>>>();
    merge_topk_kernel<1><<<BSZ, 64>>>();

    finalize_kernel<<<1, 256>>>(scal);
}